// round 6
// baseline (speedup 1.0000x reference)
#include <cuda_runtime.h>

// out[b,k] = tanh( sum_n W[k,n] * x[b,k,n] )
// B=64, K=4096, N=256 (fp32).
//
// Persistent software-pipelined variant. R1-R5 established the achieved-HBM
// wall (6.4-6.5 TB/s, exactly compulsory bytes). The one untested lever: the
// warp epilogue (5-deep SHFL chain ~130cyc + tanh + STG) has always sat
// serially between row i's loads and row i+1's loads. Here each warp issues
// the NEXT row's 4x LDG.128 before reducing the current row, so the shuffle
// latency overlaps the next memory window. Persistent grid (148*8 CTAs)
// removes 221 waves of CTA churn.

#define GK 4096
#define GN 256

__global__ __launch_bounds__(256, 8)
void ginn_pipe_kernel(const float* __restrict__ x,
                      const float* __restrict__ W,
                      float* __restrict__ out,
                      int total_rows) {
    const int lane  = threadIdx.x & 31;
    const int gwarp = (blockIdx.x * blockDim.x + threadIdx.x) >> 5;
    const int nwarp = (gridDim.x * blockDim.x) >> 5;

    const float4* __restrict__ x4 = reinterpret_cast<const float4*>(x);
    const float4* __restrict__ w4 = reinterpret_cast<const float4*>(W);

    int r = gwarp;
    if (r >= total_rows) return;

    // Prologue: load row r
    const float4* xp = x4 + (size_t)r * (GN / 4);
    const float4* wp = w4 + (size_t)(r & (GK - 1)) * (GN / 4);
    float4 x0 = __ldcs(xp + lane);
    float4 x1 = __ldcs(xp + lane + 32);
    float4 w0 = __ldg(wp + lane);
    float4 w1 = __ldg(wp + lane + 32);

    for (;;) {
        const int rn = r + nwarp;
        const bool more = rn < total_rows;

        // Issue next row's loads BEFORE reducing current row.
        float4 y0, y1, v0, v1;
        if (more) {
            const float4* xq = x4 + (size_t)rn * (GN / 4);
            const float4* wq = w4 + (size_t)(rn & (GK - 1)) * (GN / 4);
            y0 = __ldcs(xq + lane);
            y1 = __ldcs(xq + lane + 32);
            v0 = __ldg(wq + lane);
            v1 = __ldg(wq + lane + 32);
        }

        // Reduce current row (overlaps the in-flight loads above).
        float s = x0.x * w0.x;
        s = fmaf(x0.y, w0.y, s);
        s = fmaf(x0.z, w0.z, s);
        s = fmaf(x0.w, w0.w, s);
        s = fmaf(x1.x, w1.x, s);
        s = fmaf(x1.y, w1.y, s);
        s = fmaf(x1.z, w1.z, s);
        s = fmaf(x1.w, w1.w, s);

        #pragma unroll
        for (int off = 16; off > 0; off >>= 1)
            s += __shfl_xor_sync(0xffffffffu, s, off);

        if (lane == 0)
            __stcs(out + r, tanhf(s));

        if (!more) break;
        x0 = y0; x1 = y1; w0 = v0; w1 = v1;
        r = rn;
    }
}

extern "C" void kernel_launch(void* const* d_in, const int* in_sizes, int n_in,
                              void* d_out, int out_size) {
    const float* x = (const float*)d_in[0];  // [B, K, N] fp32
    const float* W = (const float*)d_in[1];  // [K, N] fp32
    float* out = (float*)d_out;              // [B, K] fp32

    const int total_rows = out_size;         // 262144

    // Persistent grid: 8 CTAs/SM * 148 SMs (152 on GB300 — 1184 still fits),
    // 256 threads (8 warps) each -> 9472 warps, ~28 rows per warp.
    const int blocks = 1184;
    ginn_pipe_kernel<<<blocks, 256>>>(x, W, out, total_rows);
}

// round 7
// speedup vs baseline: 2.6483x; 2.6483x over previous
#include <cuda_runtime.h>

// out[b,k] = tanh( sum_n W[k,n] * x[b,k,n] )
// B=64, K=4096, N=256 (fp32). One warp per (b,k) output.
//
// FINAL (R1 structure). Six variants (warp/row, 2-row MLP, W-in-registers,
// contiguous streams, .cs/.ldg hints, persistent pipeline) all establish the
// achieved-HBM wall: 6.4-6.5 TB/s (81-82% of 8 TB/s spec) moving exactly the
// compulsory 276 MB. This simplest form measured the highest DRAM% (82.2%)
// and best time (42.6us ncu): fresh warps per row mean zero load
// dependencies — the CTA scheduler pipelines the stream for free.

#define GK 4096
#define GN 256

__global__ __launch_bounds__(256, 8)
void ginn_input_kernel(const float* __restrict__ x,
                       const float* __restrict__ W,
                       float* __restrict__ out,
                       int total_outputs) {
    int warp = (blockIdx.x * blockDim.x + threadIdx.x) >> 5;
    int lane = threadIdx.x & 31;
    if (warp >= total_outputs) return;

    int k = warp & (GK - 1);  // K = 4096 (power of 2)

    const float4* __restrict__ xp =
        reinterpret_cast<const float4*>(x + (size_t)warp * GN);
    const float4* __restrict__ wp =
        reinterpret_cast<const float4*>(W + (size_t)k * GN);

    // 256 floats = 64 float4; 32 lanes * 2 iterations, front-batched.
    float4 x0 = xp[lane];
    float4 w0 = wp[lane];
    float4 x1 = xp[lane + 32];
    float4 w1 = wp[lane + 32];

    float s = x0.x * w0.x;
    s = fmaf(x0.y, w0.y, s);
    s = fmaf(x0.z, w0.z, s);
    s = fmaf(x0.w, w0.w, s);
    s = fmaf(x1.x, w1.x, s);
    s = fmaf(x1.y, w1.y, s);
    s = fmaf(x1.z, w1.z, s);
    s = fmaf(x1.w, w1.w, s);

    // butterfly reduce across the warp
    #pragma unroll
    for (int off = 16; off > 0; off >>= 1)
        s += __shfl_xor_sync(0xffffffffu, s, off);

    if (lane == 0)
        out[warp] = tanhf(s);
}

extern "C" void kernel_launch(void* const* d_in, const int* in_sizes, int n_in,
                              void* d_out, int out_size) {
    const float* x = (const float*)d_in[0];  // [B, K, N] fp32
    const float* W = (const float*)d_in[1];  // [K, N] fp32
    float* out = (float*)d_out;              // [B, K] fp32

    const int total_outputs = out_size;      // B*K = 262144
    const int threads = 256;                 // 8 warps/block -> 8 outputs/block
    const int warps_per_block = threads / 32;
    const int blocks = (total_outputs + warps_per_block - 1) / warps_per_block;

    ginn_input_kernel<<<blocks, threads>>>(x, W, out, total_outputs);
}